// round 13
// baseline (speedup 1.0000x reference)
#include <cuda_runtime.h>
#include <cuda_fp16.h>

// Problem dims (fixed)
#define BATCH 4
#define SEQ   2048
#define DIM   1024
#define ROWS  (BATCH * SEQ)        // 8192

// ---------------- scratch (device globals; no allocation allowed) ----------
__device__ __half g_xh[ROWS * DIM];             // x fp16
__device__ __half g_Wvh[DIM * DIM];             // Wv fp16
__device__ __half g_WqT[DIM * DIM];             // Wq^T fp16
__device__ __half g_WkT[DIM * DIM];             // Wk^T fp16
__device__ __half g_BM[DIM * DIM];              // B_M[d][d'] = sum_e Wk[e][d] Wq[e][d']
__device__ __half g_uh[ROWS * DIM];             // u = x * (Wq^T Wk)
__device__ __half g_vTh[BATCH * DIM * SEQ];     // v^T per batch
__device__ __half g_eh[BATCH * SEQ * SEQ];      // E = exp(scores')
__device__ float  g_rsum[ROWS];                 // row sums of E
__device__ float  g_wc[DIM];                    // Wk^T bq
__device__ float  g_c[ROWS];                    // c_j = x_j . wc

// ---------------- helpers --------------------------------------------------
__device__ __forceinline__ unsigned smem_u32(const void* p) {
    return (unsigned)__cvta_generic_to_shared(p);
}

#define CP_ASYNC16(dst_u32, src_ptr) \
    asm volatile("cp.async.cg.shared.global [%0], [%1], 16;\n" :: "r"(dst_u32), "l"(src_ptr))
#define CP_COMMIT() asm volatile("cp.async.commit_group;\n" ::)
#define CP_WAIT1()  asm volatile("cp.async.wait_group 1;\n" ::)

__device__ __forceinline__ void ldm_x4(unsigned addr, unsigned& r0, unsigned& r1,
                                       unsigned& r2, unsigned& r3) {
    asm volatile("ldmatrix.sync.aligned.m8n8.x4.shared.b16 {%0,%1,%2,%3}, [%4];\n"
                 : "=r"(r0), "=r"(r1), "=r"(r2), "=r"(r3) : "r"(addr));
}

__device__ __forceinline__ void mma_f16(float& d0, float& d1, float& d2, float& d3,
                                        unsigned a0, unsigned a1, unsigned a2, unsigned a3,
                                        unsigned b0, unsigned b1) {
    asm volatile("mma.sync.aligned.m16n8k16.row.col.f32.f16.f16.f32 "
                 "{%0,%1,%2,%3}, {%4,%5,%6,%7}, {%8,%9}, {%0,%1,%2,%3};\n"
                 : "+f"(d0), "+f"(d1), "+f"(d2), "+f"(d3)
                 : "r"(a0), "r"(a1), "r"(a2), "r"(a3), "r"(b0), "r"(b1));
}

// ---------------- fp16 NT GEMM: C[m,n] = sum_k A[m,k]*B[n,k] ---------------
// outMode 0: fp32 C, val*scale
// outMode 1: fp16 C (+bias per biasMode)
// outMode 2: fp16 C = exp(val*scale)
// outMode 3: fp32 C = val * (1/rsum[z*SEQ+row])   (rsum via 'bias')
// outMode 4: fp16 C = exp(val*scale + bias[z*SEQ+col]*scale)
// biasMode 0: none, 1: bias[col], 2: bias[row]
#define STAGES 3
#define SMEM_ELEMS_PER (STAGES * 128 * 40)
#define GEMM_SMEM_BYTES (2 * SMEM_ELEMS_PER * 2)

__global__ __launch_bounds__(256, 2)
void gemm_f16_nt(const __half* __restrict__ A,
                 const __half* __restrict__ B,
                 const float* __restrict__ bias,
                 void* __restrict__ Cout,
                 int M, int N, int K,
                 long sA, long sB, long sC,
                 float scale, int outMode, int biasMode)
{
    extern __shared__ __half smem[];

    const int z = blockIdx.z;
    A += (long)z * sA;
    B += (long)z * sB;

    const int tid  = threadIdx.x;
    const int lane = tid & 31;
    const int warp = tid >> 5;
    const int wm   = warp & 1;
    const int wn   = warp >> 1;
    const int bm   = blockIdx.y * 128;
    const int bn   = blockIdx.x * 128;

    const unsigned sbase  = smem_u32(smem);
    const unsigned sbaseB = sbase + SMEM_ELEMS_PER * 2;

    const int ldRow = tid >> 1;
    const int ldCC  = (tid & 1) * 2;
    const __half* Abase = A + (long)(bm + ldRow) * K + ldCC * 8;
    const __half* Bbase = B + (long)(bn + ldRow) * K + ldCC * 8;
    const unsigned aDstBase = sbase  + (unsigned)((ldRow * 40 + ldCC * 8) * 2);
    const unsigned bDstBase = sbaseB + (unsigned)((ldRow * 40 + ldCC * 8) * 2);

    const int nIter = K / 32;

    #pragma unroll
    for (int s = 0; s < STAGES - 1; s++) {
        long koff = (long)s * 32;
        unsigned so = (unsigned)(s * 128 * 40 * 2);
        CP_ASYNC16(aDstBase + so,      Abase + koff);
        CP_ASYNC16(aDstBase + so + 16, Abase + koff + 8);
        CP_ASYNC16(bDstBase + so,      Bbase + koff);
        CP_ASYNC16(bDstBase + so + 16, Bbase + koff + 8);
        CP_COMMIT();
    }

    float acc[4][4][4];
    #pragma unroll
    for (int i = 0; i < 4; i++)
        #pragma unroll
        for (int j = 0; j < 4; j++)
            #pragma unroll
            for (int t = 0; t < 4; t++) acc[i][j][t] = 0.0f;

    const int aRow = wm * 64 + (lane & 15);
    const int aColSel = (lane >> 4) * 8;
    const int bRow = wn * 32 + (lane & 7) + ((lane >> 4) << 3);
    const int bColSel = ((lane >> 3) & 1) * 8;

    int readS = 0, writeS = STAGES - 1;

    for (int it = 0; it < nIter; it++) {
        CP_WAIT1();
        __syncthreads();

        if (it + STAGES - 1 < nIter) {
            long koff = (long)(it + STAGES - 1) * 32;
            unsigned so = (unsigned)(writeS * 128 * 40 * 2);
            CP_ASYNC16(aDstBase + so,      Abase + koff);
            CP_ASYNC16(aDstBase + so + 16, Abase + koff + 8);
            CP_ASYNC16(bDstBase + so,      Bbase + koff);
            CP_ASYNC16(bDstBase + so + 16, Bbase + koff + 8);
        }
        CP_COMMIT();

        const unsigned stA = sbase  + (unsigned)(readS * 128 * 40 * 2);
        const unsigned stB = sbaseB + (unsigned)(readS * 128 * 40 * 2);
        #pragma unroll
        for (int kk = 0; kk < 2; kk++) {
            unsigned a[4][4], bfr[2][4];
            #pragma unroll
            for (int mt = 0; mt < 4; mt++) {
                unsigned addr = stA + (unsigned)(((aRow + mt * 16) * 40 +
                                                 kk * 16 + aColSel) * 2);
                ldm_x4(addr, a[mt][0], a[mt][1], a[mt][2], a[mt][3]);
            }
            #pragma unroll
            for (int nt2 = 0; nt2 < 2; nt2++) {
                unsigned addr = stB + (unsigned)(((bRow + nt2 * 16) * 40 +
                                                 kk * 16 + bColSel) * 2);
                ldm_x4(addr, bfr[nt2][0], bfr[nt2][1], bfr[nt2][2], bfr[nt2][3]);
            }
            #pragma unroll
            for (int mt = 0; mt < 4; mt++) {
                #pragma unroll
                for (int nt2 = 0; nt2 < 2; nt2++) {
                    mma_f16(acc[mt][2*nt2][0], acc[mt][2*nt2][1],
                            acc[mt][2*nt2][2], acc[mt][2*nt2][3],
                            a[mt][0], a[mt][1], a[mt][2], a[mt][3],
                            bfr[nt2][0], bfr[nt2][1]);
                    mma_f16(acc[mt][2*nt2+1][0], acc[mt][2*nt2+1][1],
                            acc[mt][2*nt2+1][2], acc[mt][2*nt2+1][3],
                            a[mt][0], a[mt][1], a[mt][2], a[mt][3],
                            bfr[nt2][2], bfr[nt2][3]);
                }
            }
        }
        readS = (readS + 1) % STAGES;
        writeS = (writeS + 1) % STAGES;
    }

    // ---------------- epilogue ----------------
    const int r0 = lane >> 2;
    const int c0 = (lane & 3) * 2;

    #pragma unroll
    for (int mt = 0; mt < 4; mt++) {
        float inv0 = 1.0f, inv1 = 1.0f;
        if (outMode == 3) {
            int m0r = bm + wm * 64 + mt * 16 + r0;
            inv0 = 1.0f / bias[z * SEQ + m0r];
            inv1 = 1.0f / bias[z * SEQ + m0r + 8];
        }
        #pragma unroll
        for (int nt = 0; nt < 4; nt++) {
            int m0 = bm + wm * 64 + mt * 16 + r0;
            int n0 = bn + wn * 32 + nt * 8 + c0;
            float v00 = acc[mt][nt][0] * scale, v01 = acc[mt][nt][1] * scale;
            float v10 = acc[mt][nt][2] * scale, v11 = acc[mt][nt][3] * scale;

            if (outMode == 0) {
                float* Cf = (float*)Cout + (long)z * sC;
                float2 t0; t0.x = v00; t0.y = v01;
                float2 t1; t1.x = v10; t1.y = v11;
                *(float2*)&Cf[(long)m0 * N + n0]       = t0;
                *(float2*)&Cf[(long)(m0 + 8) * N + n0] = t1;
            } else if (outMode == 3) {
                float* Cf = (float*)Cout + (long)z * sC;
                float2 t0; t0.x = v00 * inv0; t0.y = v01 * inv0;
                float2 t1; t1.x = v10 * inv1; t1.y = v11 * inv1;
                *(float2*)&Cf[(long)m0 * N + n0]       = t0;
                *(float2*)&Cf[(long)(m0 + 8) * N + n0] = t1;
            } else {
                if (outMode == 2) {
                    v00 = __expf(v00); v01 = __expf(v01);
                    v10 = __expf(v10); v11 = __expf(v11);
                } else if (outMode == 4) {
                    float cb0 = bias[z * SEQ + n0] * scale;
                    float cb1 = bias[z * SEQ + n0 + 1] * scale;
                    v00 = __expf(v00 + cb0); v01 = __expf(v01 + cb1);
                    v10 = __expf(v10 + cb0); v11 = __expf(v11 + cb1);
                } else if (biasMode == 1) {
                    float b0 = bias[n0], b1 = bias[n0 + 1];
                    v00 += b0; v01 += b1; v10 += b0; v11 += b1;
                } else if (biasMode == 2) {
                    float br0 = bias[m0], br1 = bias[m0 + 8];
                    v00 += br0; v01 += br0; v10 += br1; v11 += br1;
                }
                __half* Cb = (__half*)Cout + (long)z * sC;
                __half2 p0; p0.x = __float2half_rn(v00); p0.y = __float2half_rn(v01);
                __half2 p1; p1.x = __float2half_rn(v10); p1.y = __float2half_rn(v11);
                *(__half2*)&Cb[(long)m0 * N + n0]       = p0;
                *(__half2*)&Cb[(long)(m0 + 8) * N + n0] = p1;
            }
        }
    }
}

// ---------------- fused fp32 -> fp16 convert (x, Wv) -----------------------
__global__ __launch_bounds__(256)
void convert_all(const float* __restrict__ x, const float* __restrict__ Wv,
                 __half* __restrict__ xh, __half* __restrict__ Wvh)
{
    long b = blockIdx.x;
    const float* src;
    __half* dst;
    long off;
    if (b < 8192) { src = x;  dst = xh;  off = b; }
    else          { src = Wv; dst = Wvh; off = b - 8192; }

    long i = (off * 256 + threadIdx.x) * 4;
    float4 v = *(const float4*)(src + i);
    __half2 a, c;
    a.x = __float2half_rn(v.x); a.y = __float2half_rn(v.y);
    c.x = __float2half_rn(v.z); c.y = __float2half_rn(v.w);
    *(__half2*)(dst + i)     = a;
    *(__half2*)(dst + i + 2) = c;
}

// ---------------- fp32 [1024,1024] -> fp16 transpose -----------------------
__global__ __launch_bounds__(256)
void transpose_w(const float* __restrict__ in, __half* __restrict__ out)
{
    __shared__ float t[32][33];
    const int bx = blockIdx.x * 32, by = blockIdx.y * 32;
    const int tx = threadIdx.x, ty = threadIdx.y;   // block (32,8)
    #pragma unroll
    for (int i = 0; i < 4; i++) {
        int r = by + ty + i * 8;
        t[ty + i * 8][tx] = in[(long)r * DIM + bx + tx];
    }
    __syncthreads();
    #pragma unroll
    for (int i = 0; i < 4; i++) {
        int r = bx + ty + i * 8;
        out[(long)r * DIM + by + tx] = __float2half_rn(t[tx][ty + i * 8]);
    }
}

// ---------------- wc[d] = sum_e Wk[e][d] * bq[e] ----------------------------
__global__ __launch_bounds__(256)
void wc_kernel(const float* __restrict__ Wk, const float* __restrict__ bq,
               float* __restrict__ wc)
{
    const int d = blockIdx.x * 256 + threadIdx.x;
    float acc = 0.0f;
    for (int e = 0; e < DIM; e++)
        acc += Wk[(long)e * DIM + d] * __ldg(bq + e);
    wc[d] = acc;
}

// ---------------- c[r] = sum_d xh[r][d] * wc[d] -----------------------------
__global__ __launch_bounds__(256)
void cvec_kernel(const __half* __restrict__ xh, const float* __restrict__ wc,
                 float* __restrict__ c)
{
    const long r = blockIdx.x;
    const __half2* row = (const __half2*)(xh + r * DIM);
    const int tid = threadIdx.x;

    float sum = 0.0f;
    #pragma unroll
    for (int i = 0; i < 2; i++) {
        int idx = tid + i * 256;        // half2 index, 512 total
        __half2 h = row[idx];
        float2 f = __half22float2(h);
        sum += f.x * wc[idx * 2] + f.y * wc[idx * 2 + 1];
    }
    #pragma unroll
    for (int o = 16; o > 0; o >>= 1)
        sum += __shfl_xor_sync(0xffffffffu, sum, o);

    __shared__ float ssum[8];
    if ((tid & 31) == 0) ssum[tid >> 5] = sum;
    __syncthreads();
    if (tid == 0) {
        float t = 0.0f;
        #pragma unroll
        for (int i = 0; i < 8; i++) t += ssum[i];
        c[r] = t;
    }
}

// ---------------- row sums of fp16 E ---------------------------------------
__global__ __launch_bounds__(256)
void rowsum_h(const __half* __restrict__ E, float* __restrict__ rsum)
{
    const long r = blockIdx.x;
    const __half2* row = (const __half2*)(E + r * SEQ);
    const int tid = threadIdx.x;

    float sum = 0.0f;
    #pragma unroll
    for (int i = 0; i < 4; i++) {
        __half2 h = row[tid + i * 256];
        float2 f = __half22float2(h);
        sum += f.x + f.y;
    }
    #pragma unroll
    for (int o = 16; o > 0; o >>= 1)
        sum += __shfl_xor_sync(0xffffffffu, sum, o);

    __shared__ float ssum[8];
    if ((tid & 31) == 0) ssum[tid >> 5] = sum;
    __syncthreads();
    if (tid == 0) {
        float t = 0.0f;
        #pragma unroll
        for (int i = 0; i < 8; i++) t += ssum[i];
        rsum[r] = t;
    }
}

// ---------------- launch ---------------------------------------------------
extern "C" void kernel_launch(void* const* d_in, const int* in_sizes, int n_in,
                              void* d_out, int out_size)
{
    const float* x  = (const float*)d_in[0];
    const float* Wq = (const float*)d_in[1];
    const float* bq = (const float*)d_in[2];
    const float* Wk = (const float*)d_in[3];
    const float* bk = (const float*)d_in[4];   // cancels in softmax (row term)
    const float* Wv = (const float*)d_in[5];
    const float* bv = (const float*)d_in[6];
    float* out = (float*)d_out;
    (void)bk;

    __half *xh, *Wvh, *WqT, *WkT, *BM, *uh, *vTh, *eh;
    float *rsum, *wc, *c;
    cudaGetSymbolAddress((void**)&xh, g_xh);
    cudaGetSymbolAddress((void**)&Wvh, g_Wvh);
    cudaGetSymbolAddress((void**)&WqT, g_WqT);
    cudaGetSymbolAddress((void**)&WkT, g_WkT);
    cudaGetSymbolAddress((void**)&BM, g_BM);
    cudaGetSymbolAddress((void**)&uh, g_uh);
    cudaGetSymbolAddress((void**)&vTh, g_vTh);
    cudaGetSymbolAddress((void**)&eh, g_eh);
    cudaGetSymbolAddress((void**)&rsum, g_rsum);
    cudaGetSymbolAddress((void**)&wc, g_wc);
    cudaGetSymbolAddress((void**)&c, g_c);

    cudaFuncSetAttribute(gemm_f16_nt,
                         cudaFuncAttributeMaxDynamicSharedMemorySize,
                         GEMM_SMEM_BYTES);

    static cudaStream_t s2 = nullptr, s3 = nullptr;
    static cudaEvent_t eConv = nullptr, eC = nullptr, eV = nullptr;
    if (s2 == nullptr) {
        cudaStreamCreateWithFlags(&s2, cudaStreamNonBlocking);
        cudaStreamCreateWithFlags(&s3, cudaStreamNonBlocking);
        cudaEventCreateWithFlags(&eConv, cudaEventDisableTiming);
        cudaEventCreateWithFlags(&eC,    cudaEventDisableTiming);
        cudaEventCreateWithFlags(&eV,    cudaEventDisableTiming);
    }

    dim3 blk(256);

    // s2: wc = Wk^T bq (needs only raw inputs; starts immediately)
    wc_kernel<<<DIM / 256, blk, 0, s2>>>(Wk, bq, wc);

    // base: conversions + W transposes
    convert_all<<<9216, blk>>>(x, Wv, xh, Wvh);
    {
        dim3 gT(32, 32), bT(32, 8);
        transpose_w<<<gT, bT>>>(Wq, WqT);
        transpose_w<<<gT, bT>>>(Wk, WkT);
    }

    cudaEventRecord(eConv, 0);
    cudaStreamWaitEvent(s2, eConv, 0);
    cudaStreamWaitEvent(s3, eConv, 0);

    // s3: vT[b] = Wv @ x[b]^T + bv(row)   [1024, 2048] per batch
    {
        dim3 g(SEQ / 128, DIM / 128, BATCH);
        gemm_f16_nt<<<g, blk, GEMM_SMEM_BYTES, s3>>>(Wvh, xh, bv, vTh,
            DIM, SEQ, DIM,
            0, (long)SEQ * DIM, (long)DIM * SEQ, 1.0f, 1, 2);
    }

    // s2: c = xh . wc
    cvec_kernel<<<ROWS, blk, 0, s2>>>(xh, wc, c);
    cudaEventRecord(eC, s2);

    // base: B_M[d][d'] = sum_e WkT[d][e]*WqT[d'][e]  (64 tiles)
    {
        dim3 g(DIM / 128, DIM / 128, 1);
        gemm_f16_nt<<<g, blk, GEMM_SMEM_BYTES, 0>>>(WkT, WqT, nullptr, BM,
            DIM, DIM, DIM, 0, 0, 0, 1.0f, 1, 0);
    }

    // base: u = x . M   (u[i][d] = sum_{d'} x[i][d'] * BM[d][d'])
    {
        dim3 g(DIM / 128, ROWS / 128, 1);
        gemm_f16_nt<<<g, blk, GEMM_SMEM_BYTES, 0>>>(xh, BM, nullptr, uh,
            ROWS, DIM, DIM, 0, 0, 0, 1.0f, 1, 0);
    }

    // join c before scores
    cudaStreamWaitEvent(0, eC, 0);

    // base: E[b] = exp((u[b] . x[b]^T + c_j) / 32)   (row term cancels in softmax)
    {
        dim3 g(SEQ / 128, SEQ / 128, BATCH);
        gemm_f16_nt<<<g, blk, GEMM_SMEM_BYTES, 0>>>(uh, xh, c, eh,
            SEQ, SEQ, DIM,
            (long)SEQ * DIM, (long)SEQ * DIM, (long)SEQ * SEQ,
            0.03125f, 4, 0);
    }

    rowsum_h<<<ROWS, blk>>>(eh, rsum);

    // join vT before AV
    cudaEventRecord(eV, s3);
    cudaStreamWaitEvent(0, eV, 0);

    // base: out[b] = (E[b] @ vT[b]^T) / rsum[row]
    {
        dim3 g(DIM / 128, SEQ / 128, BATCH);
        gemm_f16_nt<<<g, blk, GEMM_SMEM_BYTES, 0>>>(eh, vTh, rsum, out,
            SEQ, DIM, SEQ,
            (long)SEQ * SEQ, (long)DIM * SEQ, (long)SEQ * DIM,
            1.0f, 3, 0);
    }
}

// round 15
// speedup vs baseline: 1.0504x; 1.0504x over previous
#include <cuda_runtime.h>
#include <cuda_fp16.h>

// Problem dims (fixed)
#define BATCH 4
#define SEQ   2048
#define DIM   1024
#define ROWS  (BATCH * SEQ)        // 8192

// ---------------- scratch (device globals; no allocation allowed) ----------
__device__ __half g_xh[ROWS * DIM];             // x fp16
__device__ __half g_Wvh[DIM * DIM];             // Wv fp16
__device__ __half g_WqT[DIM * DIM];             // Wq^T fp16
__device__ __half g_WkT[DIM * DIM];             // Wk^T fp16
__device__ __half g_BM[DIM * DIM];              // M[d][d'] = sum_e Wk[e][d] Wq[e][d']
__device__ __half g_uh[ROWS * DIM];             // u = x . M
__device__ __half g_vTh[BATCH * DIM * SEQ];     // v^T per batch
__device__ __half g_eh[BATCH * SEQ * SEQ];      // E = exp(scores')
__device__ float  g_rsum[ROWS];                 // row sums of E
__device__ float  g_wc[DIM];                    // Wk^T bq
__device__ float  g_c[ROWS];                    // c_j = x_j . wc

// ---------------- helpers --------------------------------------------------
__device__ __forceinline__ unsigned smem_u32(const void* p) {
    return (unsigned)__cvta_generic_to_shared(p);
}

#define CP_ASYNC16(dst_u32, src_ptr) \
    asm volatile("cp.async.cg.shared.global [%0], [%1], 16;\n" :: "r"(dst_u32), "l"(src_ptr))
#define CP_COMMIT() asm volatile("cp.async.commit_group;\n" ::)
#define CP_WAIT1()  asm volatile("cp.async.wait_group 1;\n" ::)

__device__ __forceinline__ void ldm_x4(unsigned addr, unsigned& r0, unsigned& r1,
                                       unsigned& r2, unsigned& r3) {
    asm volatile("ldmatrix.sync.aligned.m8n8.x4.shared.b16 {%0,%1,%2,%3}, [%4];\n"
                 : "=r"(r0), "=r"(r1), "=r"(r2), "=r"(r3) : "r"(addr));
}

__device__ __forceinline__ void mma_f16(float& d0, float& d1, float& d2, float& d3,
                                        unsigned a0, unsigned a1, unsigned a2, unsigned a3,
                                        unsigned b0, unsigned b1) {
    asm volatile("mma.sync.aligned.m16n8k16.row.col.f32.f16.f16.f32 "
                 "{%0,%1,%2,%3}, {%4,%5,%6,%7}, {%8,%9}, {%0,%1,%2,%3};\n"
                 : "+f"(d0), "+f"(d1), "+f"(d2), "+f"(d3)
                 : "r"(a0), "r"(a1), "r"(a2), "r"(a3), "r"(b0), "r"(b1));
}

// ---------------- fp16 NT GEMM: C[m,n] = sum_k A[m,k]*B[n,k] ---------------
// outMode 0: fp32 C, val*scale
// outMode 1: fp16 C (+bias per biasMode)
// outMode 2: fp16 C = exp(val*scale)
// outMode 3: fp32 C = val * (1/rsum[z*SEQ+row])   (rsum via 'bias')
// outMode 4: fp16 C = exp(val*scale + bias[z*SEQ+col]*scale)
// biasMode 0: none, 1: bias[col], 2: bias[row]
#define STAGES 3
#define SMEM_ELEMS_PER (STAGES * 128 * 40)
#define GEMM_SMEM_BYTES (2 * SMEM_ELEMS_PER * 2)

__global__ __launch_bounds__(256, 2)
void gemm_f16_nt(const __half* __restrict__ A,
                 const __half* __restrict__ B,
                 const float* __restrict__ bias,
                 void* __restrict__ Cout,
                 int M, int N, int K,
                 long sA, long sB, long sC,
                 float scale, int outMode, int biasMode)
{
    extern __shared__ __half smem[];

    const int z = blockIdx.z;
    A += (long)z * sA;
    B += (long)z * sB;

    const int tid  = threadIdx.x;
    const int lane = tid & 31;
    const int warp = tid >> 5;
    const int wm   = warp & 1;
    const int wn   = warp >> 1;
    const int bm   = blockIdx.y * 128;
    const int bn   = blockIdx.x * 128;

    const unsigned sbase  = smem_u32(smem);
    const unsigned sbaseB = sbase + SMEM_ELEMS_PER * 2;

    const int ldRow = tid >> 1;
    const int ldCC  = (tid & 1) * 2;
    const __half* Abase = A + (long)(bm + ldRow) * K + ldCC * 8;
    const __half* Bbase = B + (long)(bn + ldRow) * K + ldCC * 8;
    const unsigned aDstBase = sbase  + (unsigned)((ldRow * 40 + ldCC * 8) * 2);
    const unsigned bDstBase = sbaseB + (unsigned)((ldRow * 40 + ldCC * 8) * 2);

    const int nIter = K / 32;

    #pragma unroll
    for (int s = 0; s < STAGES - 1; s++) {
        long koff = (long)s * 32;
        unsigned so = (unsigned)(s * 128 * 40 * 2);
        CP_ASYNC16(aDstBase + so,      Abase + koff);
        CP_ASYNC16(aDstBase + so + 16, Abase + koff + 8);
        CP_ASYNC16(bDstBase + so,      Bbase + koff);
        CP_ASYNC16(bDstBase + so + 16, Bbase + koff + 8);
        CP_COMMIT();
    }

    float acc[4][4][4];
    #pragma unroll
    for (int i = 0; i < 4; i++)
        #pragma unroll
        for (int j = 0; j < 4; j++)
            #pragma unroll
            for (int t = 0; t < 4; t++) acc[i][j][t] = 0.0f;

    const int aRow = wm * 64 + (lane & 15);
    const int aColSel = (lane >> 4) * 8;
    const int bRow = wn * 32 + (lane & 7) + ((lane >> 4) << 3);
    const int bColSel = ((lane >> 3) & 1) * 8;

    int readS = 0, writeS = STAGES - 1;

    for (int it = 0; it < nIter; it++) {
        CP_WAIT1();
        __syncthreads();

        if (it + STAGES - 1 < nIter) {
            long koff = (long)(it + STAGES - 1) * 32;
            unsigned so = (unsigned)(writeS * 128 * 40 * 2);
            CP_ASYNC16(aDstBase + so,      Abase + koff);
            CP_ASYNC16(aDstBase + so + 16, Abase + koff + 8);
            CP_ASYNC16(bDstBase + so,      Bbase + koff);
            CP_ASYNC16(bDstBase + so + 16, Bbase + koff + 8);
        }
        CP_COMMIT();

        const unsigned stA = sbase  + (unsigned)(readS * 128 * 40 * 2);
        const unsigned stB = sbaseB + (unsigned)(readS * 128 * 40 * 2);
        #pragma unroll
        for (int kk = 0; kk < 2; kk++) {
            unsigned a[4][4], bfr[2][4];
            #pragma unroll
            for (int mt = 0; mt < 4; mt++) {
                unsigned addr = stA + (unsigned)(((aRow + mt * 16) * 40 +
                                                 kk * 16 + aColSel) * 2);
                ldm_x4(addr, a[mt][0], a[mt][1], a[mt][2], a[mt][3]);
            }
            #pragma unroll
            for (int nt2 = 0; nt2 < 2; nt2++) {
                unsigned addr = stB + (unsigned)(((bRow + nt2 * 16) * 40 +
                                                 kk * 16 + bColSel) * 2);
                ldm_x4(addr, bfr[nt2][0], bfr[nt2][1], bfr[nt2][2], bfr[nt2][3]);
            }
            #pragma unroll
            for (int mt = 0; mt < 4; mt++) {
                #pragma unroll
                for (int nt2 = 0; nt2 < 2; nt2++) {
                    mma_f16(acc[mt][2*nt2][0], acc[mt][2*nt2][1],
                            acc[mt][2*nt2][2], acc[mt][2*nt2][3],
                            a[mt][0], a[mt][1], a[mt][2], a[mt][3],
                            bfr[nt2][0], bfr[nt2][1]);
                    mma_f16(acc[mt][2*nt2+1][0], acc[mt][2*nt2+1][1],
                            acc[mt][2*nt2+1][2], acc[mt][2*nt2+1][3],
                            a[mt][0], a[mt][1], a[mt][2], a[mt][3],
                            bfr[nt2][2], bfr[nt2][3]);
                }
            }
        }
        readS = (readS + 1) % STAGES;
        writeS = (writeS + 1) % STAGES;
    }

    // ---------------- epilogue ----------------
    const int r0 = lane >> 2;
    const int c0 = (lane & 3) * 2;

    #pragma unroll
    for (int mt = 0; mt < 4; mt++) {
        float inv0 = 1.0f, inv1 = 1.0f;
        if (outMode == 3) {
            int m0r = bm + wm * 64 + mt * 16 + r0;
            inv0 = 1.0f / bias[z * SEQ + m0r];
            inv1 = 1.0f / bias[z * SEQ + m0r + 8];
        }
        #pragma unroll
        for (int nt = 0; nt < 4; nt++) {
            int m0 = bm + wm * 64 + mt * 16 + r0;
            int n0 = bn + wn * 32 + nt * 8 + c0;
            float v00 = acc[mt][nt][0] * scale, v01 = acc[mt][nt][1] * scale;
            float v10 = acc[mt][nt][2] * scale, v11 = acc[mt][nt][3] * scale;

            if (outMode == 0) {
                float* Cf = (float*)Cout + (long)z * sC;
                float2 t0; t0.x = v00; t0.y = v01;
                float2 t1; t1.x = v10; t1.y = v11;
                *(float2*)&Cf[(long)m0 * N + n0]       = t0;
                *(float2*)&Cf[(long)(m0 + 8) * N + n0] = t1;
            } else if (outMode == 3) {
                float* Cf = (float*)Cout + (long)z * sC;
                float2 t0; t0.x = v00 * inv0; t0.y = v01 * inv0;
                float2 t1; t1.x = v10 * inv1; t1.y = v11 * inv1;
                *(float2*)&Cf[(long)m0 * N + n0]       = t0;
                *(float2*)&Cf[(long)(m0 + 8) * N + n0] = t1;
            } else {
                if (outMode == 2) {
                    v00 = __expf(v00); v01 = __expf(v01);
                    v10 = __expf(v10); v11 = __expf(v11);
                } else if (outMode == 4) {
                    float cb0 = bias[z * SEQ + n0] * scale;
                    float cb1 = bias[z * SEQ + n0 + 1] * scale;
                    v00 = __expf(v00 + cb0); v01 = __expf(v01 + cb1);
                    v10 = __expf(v10 + cb0); v11 = __expf(v11 + cb1);
                } else if (biasMode == 1) {
                    float b0 = bias[n0], b1 = bias[n0 + 1];
                    v00 += b0; v01 += b1; v10 += b0; v11 += b1;
                } else if (biasMode == 2) {
                    float br0 = bias[m0], br1 = bias[m0 + 8];
                    v00 += br0; v01 += br0; v10 += br1; v11 += br1;
                }
                __half* Cb = (__half*)Cout + (long)z * sC;
                __half2 p0; p0.x = __float2half_rn(v00); p0.y = __float2half_rn(v01);
                __half2 p1; p1.x = __float2half_rn(v10); p1.y = __float2half_rn(v11);
                *(__half2*)&Cb[(long)m0 * N + n0]       = p0;
                *(__half2*)&Cb[(long)(m0 + 8) * N + n0] = p1;
            }
        }
    }
}

// ---------------- fused fp32 -> fp16 convert (x, Wv) -----------------------
__global__ __launch_bounds__(256)
void convert_all(const float* __restrict__ x, const float* __restrict__ Wv,
                 __half* __restrict__ xh, __half* __restrict__ Wvh)
{
    long b = blockIdx.x;
    const float* src;
    __half* dst;
    long off;
    if (b < 8192) { src = x;  dst = xh;  off = b; }
    else          { src = Wv; dst = Wvh; off = b - 8192; }

    long i = (off * 256 + threadIdx.x) * 4;
    float4 v = *(const float4*)(src + i);
    __half2 a, c;
    a.x = __float2half_rn(v.x); a.y = __float2half_rn(v.y);
    c.x = __float2half_rn(v.z); c.y = __float2half_rn(v.w);
    *(__half2*)(dst + i)     = a;
    *(__half2*)(dst + i + 2) = c;
}

// ---------------- fp32 [1024,1024] -> fp16 transpose -----------------------
__global__ __launch_bounds__(256)
void transpose_w(const float* __restrict__ in, __half* __restrict__ out)
{
    __shared__ float t[32][33];
    const int bx = blockIdx.x * 32, by = blockIdx.y * 32;
    const int tx = threadIdx.x, ty = threadIdx.y;   // block (32,8)
    #pragma unroll
    for (int i = 0; i < 4; i++) {
        int r = by + ty + i * 8;
        t[ty + i * 8][tx] = in[(long)r * DIM + bx + tx];
    }
    __syncthreads();
    #pragma unroll
    for (int i = 0; i < 4; i++) {
        int r = bx + ty + i * 8;
        out[(long)r * DIM + by + tx] = __float2half_rn(t[tx][ty + i * 8]);
    }
}

// ---------------- wc[d] = sum_e Wk[e][d] * bq[e] ----------------------------
__global__ __launch_bounds__(256)
void wc_kernel(const float* __restrict__ Wk, const float* __restrict__ bq,
               float* __restrict__ wc)
{
    const int d = blockIdx.x * 256 + threadIdx.x;
    float acc = 0.0f;
    for (int e = 0; e < DIM; e++)
        acc += Wk[(long)e * DIM + d] * __ldg(bq + e);
    wc[d] = acc;
}

// ---------------- c[r] = sum_d xh[r][d] * wc[d] -----------------------------
__global__ __launch_bounds__(256)
void cvec_kernel(const __half* __restrict__ xh, const float* __restrict__ wc,
                 float* __restrict__ c)
{
    const long r = blockIdx.x;
    const __half2* row = (const __half2*)(xh + r * DIM);
    const int tid = threadIdx.x;

    float sum = 0.0f;
    #pragma unroll
    for (int i = 0; i < 2; i++) {
        int idx = tid + i * 256;
        __half2 h = row[idx];
        float2 f = __half22float2(h);
        sum += f.x * wc[idx * 2] + f.y * wc[idx * 2 + 1];
    }
    #pragma unroll
    for (int o = 16; o > 0; o >>= 1)
        sum += __shfl_xor_sync(0xffffffffu, sum, o);

    __shared__ float ssum[8];
    if ((tid & 31) == 0) ssum[tid >> 5] = sum;
    __syncthreads();
    if (tid == 0) {
        float t = 0.0f;
        #pragma unroll
        for (int i = 0; i < 8; i++) t += ssum[i];
        c[r] = t;
    }
}

// ---------------- row sums of fp16 E ---------------------------------------
__global__ __launch_bounds__(256)
void rowsum_h(const __half* __restrict__ E, float* __restrict__ rsum)
{
    const long r = blockIdx.x;
    const __half2* row = (const __half2*)(E + r * SEQ);
    const int tid = threadIdx.x;

    float sum = 0.0f;
    #pragma unroll
    for (int i = 0; i < 4; i++) {
        __half2 h = row[tid + i * 256];
        float2 f = __half22float2(h);
        sum += f.x + f.y;
    }
    #pragma unroll
    for (int o = 16; o > 0; o >>= 1)
        sum += __shfl_xor_sync(0xffffffffu, sum, o);

    __shared__ float ssum[8];
    if ((tid & 31) == 0) ssum[tid >> 5] = sum;
    __syncthreads();
    if (tid == 0) {
        float t = 0.0f;
        #pragma unroll
        for (int i = 0; i < 8; i++) t += ssum[i];
        rsum[r] = t;
    }
}

// ---------------- launch ---------------------------------------------------
extern "C" void kernel_launch(void* const* d_in, const int* in_sizes, int n_in,
                              void* d_out, int out_size)
{
    const float* x  = (const float*)d_in[0];
    const float* Wq = (const float*)d_in[1];
    const float* bq = (const float*)d_in[2];
    const float* Wk = (const float*)d_in[3];
    const float* bk = (const float*)d_in[4];   // cancels in softmax (row term)
    const float* Wv = (const float*)d_in[5];
    const float* bv = (const float*)d_in[6];
    float* out = (float*)d_out;
    (void)bk;

    __half *xh, *Wvh, *WqT, *WkT, *BM, *uh, *vTh, *eh;
    float *rsum, *wc, *c;
    cudaGetSymbolAddress((void**)&xh, g_xh);
    cudaGetSymbolAddress((void**)&Wvh, g_Wvh);
    cudaGetSymbolAddress((void**)&WqT, g_WqT);
    cudaGetSymbolAddress((void**)&WkT, g_WkT);
    cudaGetSymbolAddress((void**)&BM, g_BM);
    cudaGetSymbolAddress((void**)&uh, g_uh);
    cudaGetSymbolAddress((void**)&vTh, g_vTh);
    cudaGetSymbolAddress((void**)&eh, g_eh);
    cudaGetSymbolAddress((void**)&rsum, g_rsum);
    cudaGetSymbolAddress((void**)&wc, g_wc);
    cudaGetSymbolAddress((void**)&c, g_c);

    cudaFuncSetAttribute(gemm_f16_nt,
                         cudaFuncAttributeMaxDynamicSharedMemorySize,
                         GEMM_SMEM_BYTES);

    static cudaStream_t s2 = nullptr, s3 = nullptr;
    static cudaEvent_t eFork = nullptr, eConv = nullptr, eC = nullptr, eV = nullptr;
    if (s2 == nullptr) {
        cudaStreamCreateWithFlags(&s2, cudaStreamNonBlocking);
        cudaStreamCreateWithFlags(&s3, cudaStreamNonBlocking);
        cudaEventCreateWithFlags(&eFork, cudaEventDisableTiming);
        cudaEventCreateWithFlags(&eConv, cudaEventDisableTiming);
        cudaEventCreateWithFlags(&eC,    cudaEventDisableTiming);
        cudaEventCreateWithFlags(&eV,    cudaEventDisableTiming);
    }

    dim3 blk(256);

    // ---- legal fork: event on the capturing (base) stream FIRST ----
    cudaEventRecord(eFork, 0);
    cudaStreamWaitEvent(s2, eFork, 0);
    cudaStreamWaitEvent(s3, eFork, 0);

    // t=0 parallel work:
    //   base: W transposes -> BM GEMM (raw inputs only, no x dependency)
    //   s2:   wc = Wk^T bq
    //   s3:   convert x, Wv -> vT GEMM
    wc_kernel<<<DIM / 256, blk, 0, s2>>>(Wk, bq, wc);
    convert_all<<<9216, blk, 0, s3>>>(x, Wv, xh, Wvh);
    cudaEventRecord(eConv, s3);
    {
        dim3 gT(32, 32), bT(32, 8);
        transpose_w<<<gT, bT, 0, 0>>>(Wq, WqT);
        transpose_w<<<gT, bT, 0, 0>>>(Wk, WkT);
    }

    // base: BM = WkT x WqT^T (64 tiles) -- overlaps convert
    {
        dim3 g(DIM / 128, DIM / 128, 1);
        gemm_f16_nt<<<g, blk, GEMM_SMEM_BYTES, 0>>>(WkT, WqT, nullptr, BM,
            DIM, DIM, DIM, 0, 0, 0, 1.0f, 1, 0);
    }

    // s3: vT[b] = Wv @ x[b]^T + bv(row) -- right after convert on same stream
    {
        dim3 g(SEQ / 128, DIM / 128, BATCH);
        gemm_f16_nt<<<g, blk, GEMM_SMEM_BYTES, s3>>>(Wvh, xh, bv, vTh,
            DIM, SEQ, DIM,
            0, (long)SEQ * DIM, (long)DIM * SEQ, 1.0f, 1, 2);
    }

    // s2: c = xh . wc (needs xh from s3's convert)
    cudaStreamWaitEvent(s2, eConv, 0);
    cvec_kernel<<<ROWS, blk, 0, s2>>>(xh, wc, c);
    cudaEventRecord(eC, s2);

    // base: u = x . M (needs xh + BM; BM ordered on base already)
    cudaStreamWaitEvent(0, eConv, 0);
    {
        dim3 g(DIM / 128, ROWS / 128, 1);
        gemm_f16_nt<<<g, blk, GEMM_SMEM_BYTES, 0>>>(xh, BM, nullptr, uh,
            ROWS, DIM, DIM, 0, 0, 0, 1.0f, 1, 0);
    }

    // join c before scores
    cudaStreamWaitEvent(0, eC, 0);

    // base: E[b] = exp((u[b] . x[b]^T + c_j) / 32)
    {
        dim3 g(SEQ / 128, SEQ / 128, BATCH);
        gemm_f16_nt<<<g, blk, GEMM_SMEM_BYTES, 0>>>(uh, xh, c, eh,
            SEQ, SEQ, DIM,
            (long)SEQ * DIM, (long)SEQ * DIM, (long)SEQ * SEQ,
            0.03125f, 4, 0);
    }

    rowsum_h<<<ROWS, blk>>>(eh, rsum);

    // join vT before AV
    cudaEventRecord(eV, s3);
    cudaStreamWaitEvent(0, eV, 0);

    // base: out[b] = (E[b] @ vT[b]^T) / rsum[row]
    {
        dim3 g(DIM / 128, SEQ / 128, BATCH);
        gemm_f16_nt<<<g, blk, GEMM_SMEM_BYTES, 0>>>(eh, vTh, rsum, out,
            SEQ, DIM, SEQ,
            (long)SEQ * SEQ, (long)DIM * SEQ, (long)SEQ * DIM,
            1.0f, 3, 0);
    }
}